// round 2
// baseline (speedup 1.0000x reference)
#include <cuda_runtime.h>
#include <cuda_bf16.h>
#include <cstdint>

// Problem constants
#define BB 512      // batch
#define TT 365      // time steps
#define CC 10       // channels
#define PP 64       // prototypes
#define KK 3650     // T*C
#define KREAL 4015  // 3650 + 365
#define KPAD 4096

// Output layout (float32, concatenated in reference return order)
#define O_OUTSEQ 0
#define O_INSEQ  1868800
#define O_DIST   3737600
#define O_IDX    3770368
#define O_LABEL  3770880
#define O_MASK   3771392

// ---------------- scratch (device globals; no allocation allowed) ----------
__device__ float g_At[KPAD * BB];          // A^T, k-major: [k][b]   (8 MB)
__device__ float g_Wt[KPAD * PP];          // W^T, k-major: [k][p]   (1 MB)
__device__ float g_x2[BB];
__device__ float g_part[64 * BB * PP];     // K-split partials [ks][b][p] (8 MB)
__device__ int   g_idx[BB];

// ---------------- build W^T:  W[p,k] = -2*proto[p,k]  (k<3650)
//                              W[p,3650+t] = sum_c proto[p,t,c]^2
__global__ void k_buildW(const float* __restrict__ proto) {
    int idx = blockIdx.x * blockDim.x + threadIdx.x;     // over KPAD*PP
    if (idx >= KPAD * PP) return;
    int k = idx / PP;
    int p = idx % PP;
    float w = 0.0f;
    if (k < KK) {
        w = -2.0f * proto[p * KK + k];
    } else if (k < KREAL) {
        int t = k - KK;
        float s = 0.0f;
        #pragma unroll
        for (int c = 0; c < CC; c++) {
            float v = proto[p * KK + t * CC + c];
            s += v * v;
        }
        w = s;
    }
    g_Wt[k * PP + p] = w;
}

// ---------------- build A^T (k-major) with 32x32 smem transpose ------------
// A[b,k] = mask[b,t(k)]*x[b,k]  (k<3650);  A[b,3650+t] = mask[b,t];  else 0
__global__ void k_buildAT(const float* __restrict__ x,
                          const float* __restrict__ mask) {
    __shared__ float tile[32][33];
    int k0 = blockIdx.x * 32;
    int b0 = blockIdx.y * 32;
    int tx = threadIdx.x & 31;        // k within tile (load) / b (store)
    int ty = threadIdx.x >> 5;        // 0..7

    #pragma unroll
    for (int i = 0; i < 4; i++) {
        int r = ty + i * 8;           // b within tile
        int b = b0 + r;
        int k = k0 + tx;
        float v = 0.0f;
        if (k < KK) {
            int t = k / CC;
            v = x[b * KK + k] * mask[b * TT + t];
        } else if (k < KREAL) {
            v = mask[b * TT + (k - KK)];
        }
        tile[r][tx] = v;
    }
    __syncthreads();
    #pragma unroll
    for (int i = 0; i < 4; i++) {
        int r = ty + i * 8;           // k within tile
        g_At[(k0 + r) * BB + b0 + tx] = tile[tx][r];
    }
}

// ---------------- x2[b] = sum_k mask*x^2 -----------------------------------
__global__ void k_x2(const float* __restrict__ x,
                     const float* __restrict__ mask) {
    __shared__ float red[256];
    int b = blockIdx.x;
    int tid = threadIdx.x;
    float acc = 0.0f;
    for (int k = tid; k < KK; k += 256) {
        float xv = x[b * KK + k];
        acc += mask[b * TT + k / CC] * xv * xv;
    }
    red[tid] = acc;
    __syncthreads();
    for (int s = 128; s > 0; s >>= 1) {
        if (tid < s) red[tid] += red[tid + s];
        __syncthreads();
    }
    if (tid == 0) g_x2[b] = red[0];
}

// ---------------- fp32 GEMM: part[ks][b][p] = sum_{k in chunk} A^T[k][b]*W^T[k][p]
// BM=256, BN=64, chunk=64 (two 32-deep halves), 256 threads, 8x8 reg tile.
__global__ void __launch_bounds__(256, 2) k_gemm() {
    __shared__ float As[32][256];   // 32 KB
    __shared__ float Ws[32][64];    //  8 KB
    int ks = blockIdx.x;            // 0..63
    int b0 = blockIdx.y * 256;      // 0 or 256
    int tid = threadIdx.x;
    int tb = tid & 31;              // b-group: b = b0 + tb + 32j
    int tp = tid >> 5;              // p-group: p = tp*8 + i

    float acc[8][8];
    #pragma unroll
    for (int j = 0; j < 8; j++)
        #pragma unroll
        for (int i = 0; i < 8; i++) acc[j][i] = 0.0f;

    for (int h = 0; h < 2; h++) {
        int k0 = ks * 64 + h * 32;
        // stage A^T: 32 rows x 256 cols = 2048 float4 / 256 threads = 8 each
        #pragma unroll
        for (int i = 0; i < 8; i++) {
            int e = tid + i * 256;
            int row = e >> 6;
            int c4 = e & 63;
            float4 v = *reinterpret_cast<const float4*>(
                &g_At[(k0 + row) * BB + b0 + c4 * 4]);
            *reinterpret_cast<float4*>(&As[row][c4 * 4]) = v;
        }
        // stage W^T: 32 rows x 64 cols = 512 float4 / 256 threads = 2 each
        #pragma unroll
        for (int i = 0; i < 2; i++) {
            int e = tid + i * 256;
            int row = e >> 4;
            int c4 = e & 15;
            float4 v = *reinterpret_cast<const float4*>(
                &g_Wt[(k0 + row) * PP + c4 * 4]);
            *reinterpret_cast<float4*>(&Ws[row][c4 * 4]) = v;
        }
        __syncthreads();

        #pragma unroll 4
        for (int kk = 0; kk < 32; kk++) {
            float a[8];
            #pragma unroll
            for (int j = 0; j < 8; j++) a[j] = As[kk][tb + 32 * j];
            float4 w0 = *reinterpret_cast<const float4*>(&Ws[kk][tp * 8]);
            float4 w1 = *reinterpret_cast<const float4*>(&Ws[kk][tp * 8 + 4]);
            float w[8] = {w0.x, w0.y, w0.z, w0.w, w1.x, w1.y, w1.z, w1.w};
            #pragma unroll
            for (int j = 0; j < 8; j++)
                #pragma unroll
                for (int i = 0; i < 8; i++)
                    acc[j][i] += a[j] * w[i];
        }
        __syncthreads();
    }

    // write partials
    #pragma unroll
    for (int j = 0; j < 8; j++) {
        int b = b0 + tb + 32 * j;
        float* dst = &g_part[(ks * BB + b) * PP + tp * 8];
        *reinterpret_cast<float4*>(dst) =
            make_float4(acc[j][0], acc[j][1], acc[j][2], acc[j][3]);
        *reinterpret_cast<float4*>(dst + 4) =
            make_float4(acc[j][4], acc[j][5], acc[j][6], acc[j][7]);
    }
}

// ---------------- reduce partials, distances, argmin, indices, label -------
__global__ void k_reduce(const int* __restrict__ label,
                         float* __restrict__ out) {
    __shared__ float sv[64];
    __shared__ int si[64];
    int b = blockIdx.x;
    int p = threadIdx.x;   // 0..63
    float acc = g_x2[b];
    #pragma unroll 8
    for (int ks = 0; ks < 64; ks++)
        acc += g_part[(ks * BB + b) * PP + p];
    out[O_DIST + b * PP + p] = acc;

    sv[p] = acc;
    si[p] = p;
    __syncthreads();
    for (int s = 32; s > 0; s >>= 1) {
        if (p < s) {
            float ov = sv[p + s];
            int oi = si[p + s];
            if (ov < sv[p] || (ov == sv[p] && oi < si[p])) {
                sv[p] = ov;
                si[p] = oi;
            }
        }
        __syncthreads();
    }
    if (p == 0) {
        g_idx[b] = si[0];
        out[O_IDX + b] = (float)si[0];
        out[O_LABEL + b] = (float)label[b];
    }
}

// ---------------- gather selected prototype --------------------------------
__global__ void k_gather(const float* __restrict__ proto,
                         float* __restrict__ out) {
    int b = blockIdx.x;
    int idx = g_idx[b];
    const float2* src = reinterpret_cast<const float2*>(proto + idx * KK);
    float2* dst = reinterpret_cast<float2*>(out + O_OUTSEQ + b * KK);
    for (int i = threadIdx.x; i < KK / 2; i += blockDim.x)
        dst[i] = src[i];
}

// ---------------- launcher --------------------------------------------------
extern "C" void kernel_launch(void* const* d_in, const int* in_sizes, int n_in,
                              void* d_out, int out_size) {
    const float* x     = (const float*)d_in[0];  // [B,T,C]
    const float* mask  = (const float*)d_in[1];  // [B,T]
    const int*   label = (const int*)d_in[2];    // [B]
    const float* proto = (const float*)d_in[3];  // [P,T,C]
    float* out = (float*)d_out;

    k_buildW<<<(KPAD * PP + 255) / 256, 256>>>(proto);
    k_buildAT<<<dim3(KPAD / 32, BB / 32), 256>>>(x, mask);
    k_x2<<<BB, 256>>>(x, mask);
    k_gemm<<<dim3(64, 2), 256>>>();
    k_reduce<<<BB, 64>>>(label, out);
    k_gather<<<BB, 256>>>(proto, out);
    cudaMemcpyAsync(out + O_INSEQ, x, (size_t)BB * KK * sizeof(float),
                    cudaMemcpyDeviceToDevice);
    cudaMemcpyAsync(out + O_MASK, mask, (size_t)BB * TT * sizeof(float),
                    cudaMemcpyDeviceToDevice);
}

// round 3
// speedup vs baseline: 1.1837x; 1.1837x over previous
#include <cuda_runtime.h>
#include <cuda_bf16.h>
#include <cstdint>

// Problem constants
#define BB 512      // batch
#define TT 365      // time steps
#define CC 10       // channels
#define PP 64       // prototypes
#define KK 3650     // T*C
#define KREAL 4015  // 3650 + 365
#define KPAD 4096

// Output layout (float32, concatenated in reference return order)
#define O_OUTSEQ 0
#define O_INSEQ  1868800
#define O_DIST   3737600
#define O_IDX    3770368
#define O_LABEL  3770880
#define O_MASK   3771392

// ---------------- scratch (device globals; no allocation allowed) ----------
__device__ float g_Wt[KPAD * PP];          // W^T, k-major: [k][p]   (1 MB)
__device__ float g_part[64 * BB * PP];     // K-split partials [ks][b][p] (8 MB)
__device__ float g_x2p[BB * 64];           // x2 partials [b][ks]  (128 KB)
__device__ int   g_idx[BB];

// ---------------- packed f32x2 helpers -------------------------------------
__device__ __forceinline__ void fma2(unsigned long long& d,
                                     unsigned long long a,
                                     unsigned long long b) {
    asm("fma.rn.f32x2 %0, %1, %2, %0;" : "+l"(d) : "l"(a), "l"(b));
}
__device__ __forceinline__ unsigned long long pack2(float x) {
    unsigned long long r;
    asm("mov.b64 %0, {%1, %1};" : "=l"(r) : "f"(x));
    return r;
}

// ---------------- build W^T (k-major) via 32x32 smem transpose -------------
// W[p,k] = -2*proto[p,k] (k<KK); W[p,KK+t] = sum_c proto[p,t,c]^2; else 0
__global__ void k_buildW(const float* __restrict__ proto) {
    __shared__ float tile[32][33];
    int k0 = blockIdx.x * 32;
    int p0 = blockIdx.y * 32;
    int tx = threadIdx.x & 31;
    int ty = threadIdx.x >> 5;      // 0..7

    #pragma unroll
    for (int i = 0; i < 4; i++) {
        int p = p0 + ty + i * 8;
        int k = k0 + tx;
        float v = 0.0f;
        if (k < KK) {
            v = -2.0f * proto[p * KK + k];
        } else if (k < KREAL) {
            int t = k - KK;
            float s = 0.0f;
            #pragma unroll
            for (int c = 0; c < CC; c++) {
                float q = proto[p * KK + t * CC + c];
                s += q * q;
            }
            v = s;
        }
        tile[ty + i * 8][tx] = v;   // tile[p_local][k_local]
    }
    __syncthreads();
    #pragma unroll
    for (int i = 0; i < 4; i++) {
        int k = k0 + ty + i * 8;
        g_Wt[k * PP + p0 + tx] = tile[tx][ty + i * 8];
    }
}

// ---------------- fused GEMM: stages virtual A on the fly ------------------
// A[b,k] = mask[b,k/10]*x[b,k] (k<KK); mask[b,k-KK] (KK<=k<KREAL); else 0
// part[ks][b][p] = sum_{k in 64-chunk ks} A[b,k]*W^T[k][p]
// x2p[b][ks]     = sum_{k in chunk, k<KK} A[b,k]^2     (mask^2 = mask)
// BM=128, BN=64, chunk=64 (two 32-deep halves), 256 threads, 4x8 reg tile.
__global__ void __launch_bounds__(256, 3) k_gemm(const float* __restrict__ x,
                                                 const float* __restrict__ mask) {
    __shared__ float As[128][33];   // 16.9 KB (one 32-deep half)
    __shared__ float Ws[64][64];    // 16 KB  (full 64-deep chunk)
    int ks = blockIdx.x;            // 0..63
    int k0 = ks * 64;
    int b0 = blockIdx.y * 128;      // 0,128,256,384
    int tid = threadIdx.x;
    int tb = tid & 31;              // b = b0 + tb + 32j
    int tp = tid >> 5;              // p = tp*8 + i

    // stage W^T chunk: 64x64 floats = 1024 float4 / 256 threads = 4 each
    #pragma unroll
    for (int i = 0; i < 4; i++) {
        int e = tid + i * 256;
        int row = e >> 4;
        int c4 = e & 15;
        float4 v = *reinterpret_cast<const float4*>(&g_Wt[(k0 + row) * PP + c4 * 4]);
        *reinterpret_cast<float4*>(&Ws[row][c4 * 4]) = v;
    }

    unsigned long long acc2[4][4];
    #pragma unroll
    for (int j = 0; j < 4; j++)
        #pragma unroll
        for (int i = 0; i < 4; i++) acc2[j][i] = 0ull;
    float x2a[4] = {0.f, 0.f, 0.f, 0.f};

    int kloc = tid & 31;            // staging role: k within half
    int brow0 = tid >> 5;           // staging role: b row base (0..7)

    for (int h = 0; h < 2; h++) {
        int kh = k0 + h * 32;
        int k = kh + kloc;
        bool isx = (k < KK);
        bool ism = (!isx) && (k < KREAL);
        int t = isx ? (k / CC) : (k - KK);
        if (h) __syncthreads();     // protect As reuse
        // stage A half: 128 rows x 32 cols, 16 rows per thread-group pass
        #pragma unroll
        for (int i = 0; i < 16; i++) {
            int brow = brow0 + i * 8;
            int b = b0 + brow;
            float v = 0.0f;
            if (isx)      v = x[b * KK + k] * __ldg(&mask[b * TT + t]);
            else if (ism) v = __ldg(&mask[b * TT + t]);
            As[brow][kloc] = v;
        }
        __syncthreads();

        #pragma unroll 8
        for (int kk = 0; kk < 32; kk++) {
            float a[4];
            #pragma unroll
            for (int j = 0; j < 4; j++) a[j] = As[tb + 32 * j][kk];
            const unsigned long long* wp =
                reinterpret_cast<const unsigned long long*>(&Ws[h * 32 + kk][tp * 8]);
            unsigned long long w0 = wp[0], w1 = wp[1], w2 = wp[2], w3 = wp[3];
            #pragma unroll
            for (int j = 0; j < 4; j++) {
                unsigned long long aj = pack2(a[j]);
                fma2(acc2[j][0], aj, w0);
                fma2(acc2[j][1], aj, w1);
                fma2(acc2[j][2], aj, w2);
                fma2(acc2[j][3], aj, w3);
            }
            if (tp == 0 && (kh + kk) < KK) {
                #pragma unroll
                for (int j = 0; j < 4; j++) x2a[j] += a[j] * a[j];
            }
        }
    }

    // write partials
    #pragma unroll
    for (int j = 0; j < 4; j++) {
        int b = b0 + tb + 32 * j;
        float2 p0v = *reinterpret_cast<float2*>(&acc2[j][0]);
        float2 p1v = *reinterpret_cast<float2*>(&acc2[j][1]);
        float2 p2v = *reinterpret_cast<float2*>(&acc2[j][2]);
        float2 p3v = *reinterpret_cast<float2*>(&acc2[j][3]);
        float* dst = &g_part[(ks * BB + b) * PP + tp * 8];
        *reinterpret_cast<float4*>(dst)     = make_float4(p0v.x, p0v.y, p1v.x, p1v.y);
        *reinterpret_cast<float4*>(dst + 4) = make_float4(p2v.x, p2v.y, p3v.x, p3v.y);
    }
    if (tp == 0) {
        #pragma unroll
        for (int j = 0; j < 4; j++)
            g_x2p[(b0 + tb + 32 * j) * 64 + ks] = x2a[j];
    }
}

// ---------------- reduce partials, distances, argmin, indices, label -------
__global__ void k_reduce(const int* __restrict__ label,
                         float* __restrict__ out) {
    __shared__ float sx[64];
    __shared__ float sv[64];
    __shared__ int si[64];
    int b = blockIdx.x;
    int p = threadIdx.x;            // 0..63

    sx[p] = g_x2p[b * 64 + p];      // ks = p
    __syncthreads();
    for (int s = 32; s > 0; s >>= 1) {
        if (p < s) sx[p] += sx[p + s];
        __syncthreads();
    }
    float acc = sx[0];
    #pragma unroll 8
    for (int ks = 0; ks < 64; ks++)
        acc += g_part[(ks * BB + b) * PP + p];
    out[O_DIST + b * PP + p] = acc;

    sv[p] = acc;
    si[p] = p;
    __syncthreads();
    for (int s = 32; s > 0; s >>= 1) {
        if (p < s) {
            float ov = sv[p + s];
            int oi = si[p + s];
            if (ov < sv[p] || (ov == sv[p] && oi < si[p])) {
                sv[p] = ov;
                si[p] = oi;
            }
        }
        __syncthreads();
    }
    if (p == 0) {
        g_idx[b] = si[0];
        out[O_IDX + b] = (float)si[0];
        out[O_LABEL + b] = (float)label[b];
    }
}

// ---------------- gather selected prototype + pass-through copies ----------
__global__ void k_gather_copy(const float* __restrict__ x,
                              const float* __restrict__ mask,
                              const float* __restrict__ proto,
                              float* __restrict__ out) {
    int b = blockIdx.x;
    int idx = g_idx[b];
    const float2* src = reinterpret_cast<const float2*>(proto + idx * KK);
    const float2* xs  = reinterpret_cast<const float2*>(x + b * KK);
    float2* d0 = reinterpret_cast<float2*>(out + O_OUTSEQ + b * KK);
    float2* d1 = reinterpret_cast<float2*>(out + O_INSEQ + b * KK);
    for (int i = threadIdx.x; i < KK / 2; i += blockDim.x) {
        d0[i] = src[i];
        d1[i] = xs[i];
    }
    for (int i = threadIdx.x; i < TT; i += blockDim.x)
        out[O_MASK + b * TT + i] = mask[b * TT + i];
}

// ---------------- launcher --------------------------------------------------
extern "C" void kernel_launch(void* const* d_in, const int* in_sizes, int n_in,
                              void* d_out, int out_size) {
    const float* x     = (const float*)d_in[0];  // [B,T,C]
    const float* mask  = (const float*)d_in[1];  // [B,T]
    const int*   label = (const int*)d_in[2];    // [B]
    const float* proto = (const float*)d_in[3];  // [P,T,C]
    float* out = (float*)d_out;

    k_buildW<<<dim3(KPAD / 32, PP / 32), 256>>>(proto);
    k_gemm<<<dim3(64, 4), 256>>>(x, mask);
    k_reduce<<<BB, 64>>>(label, out);
    k_gather_copy<<<BB, 256>>>(x, mask, proto, out);
}